// round 7
// baseline (speedup 1.0000x reference)
#include <cuda_runtime.h>
#include <cuda_fp16.h>
#include <cstdint>

#define LOG2E 1.4426950408889634f
#define SC2   0.18033688011112042f   // 0.125 * LOG2E
#define PSH   9.0f                   // prob scale 2^9 (cancels in normalization)

__device__ __forceinline__ uint32_t s2u(const void* p) {
    uint32_t a;
    asm("{ .reg .u64 t; cvta.to.shared.u64 t, %1; cvt.u32.u64 %0, t; }" : "=r"(a) : "l"(p));
    return a;
}
__device__ __forceinline__ void ldm4(uint32_t (&r)[4], uint32_t addr) {
    asm volatile("ldmatrix.sync.aligned.m8n8.x4.shared.b16 {%0,%1,%2,%3}, [%4];"
        : "=r"(r[0]), "=r"(r[1]), "=r"(r[2]), "=r"(r[3]) : "r"(addr));
}
__device__ __forceinline__ void mmaf16(float (&c)[4], const uint32_t (&a)[4],
                                       uint32_t b0, uint32_t b1) {
    asm volatile("mma.sync.aligned.m16n8k16.row.col.f32.f16.f16.f32 "
        "{%0,%1,%2,%3}, {%4,%5,%6,%7}, {%8,%9}, {%0,%1,%2,%3};"
        : "+f"(c[0]), "+f"(c[1]), "+f"(c[2]), "+f"(c[3])
        : "r"(a[0]), "r"(a[1]), "r"(a[2]), "r"(a[3]), "r"(b0), "r"(b1));
}
__device__ __forceinline__ void cpa16(uint32_t dst, const void* src) {
    asm volatile("cp.async.cg.shared.global [%0], [%1], 16;" :: "r"(dst), "l"(src));
}
#define CP_COMMIT() asm volatile("cp.async.commit_group;" ::: "memory")
#define CP_WAIT0()  asm volatile("cp.async.wait_group 0;" ::: "memory")
#define CP_WAIT1()  asm volatile("cp.async.wait_group 1;" ::: "memory")

__device__ __forceinline__ float ex2(float x) {
    float y; asm("ex2.approx.f32 %0, %1;" : "=f"(y) : "f"(x)); return y;
}
__device__ __forceinline__ uint32_t packh2(__half a, __half b) {
    __half2 t = __halves2half2(a, b);
    return *reinterpret_cast<uint32_t*>(&t);
}

// ---------------- device scratch (no cudaMalloc) ----------------
__device__ __align__(16) __half g_Xhi[4096 * 1024];
__device__ __align__(16) __half g_Xlo[4096 * 1024];
__device__ __align__(16) __half g_Wthi[3072 * 1024];
__device__ __align__(16) __half g_Wtlo[3072 * 1024];
__device__ __align__(16) __half g_Qhi[32 * 2048 * 64];
__device__ __align__(16) __half g_Khi[32 * 2048 * 64];
__device__ __align__(16) __half g_Vhi[32 * 64 * 2048];  // transposed [bh][hd][s]
__device__ __align__(16) __half g_Vlo[32 * 64 * 2048];

// ---------------- prep ----------------
__global__ __launch_bounds__(256) void k_split_x(const float4* __restrict__ X) {
    int i = blockIdx.x * 256 + threadIdx.x;
    float4 v = X[i];
    __half h0 = __float2half_rn(v.x), h1 = __float2half_rn(v.y);
    __half h2 = __float2half_rn(v.z), h3 = __float2half_rn(v.w);
    ((uint32_t*)g_Xhi)[2 * i] = packh2(h0, h1);
    ((uint32_t*)g_Xhi)[2 * i + 1] = packh2(h2, h3);
    ((uint32_t*)g_Xlo)[2 * i] = packh2(__float2half_rn(v.x - __half2float(h0)),
                                       __float2half_rn(v.y - __half2float(h1)));
    ((uint32_t*)g_Xlo)[2 * i + 1] = packh2(__float2half_rn(v.z - __half2float(h2)),
                                           __float2half_rn(v.w - __half2float(h3)));
}

__global__ void k_transw(const float* __restrict__ Wq, const float* __restrict__ Wk,
                         const float* __restrict__ Wv) {
    __shared__ float t[32][33];
    int z = blockIdx.z;
    const float* W = (z == 0) ? Wq : (z == 1) ? Wk : Wv;
    int n0 = blockIdx.x * 32, k0 = blockIdx.y * 32;
    int tx = threadIdx.x, ty = threadIdx.y;
#pragma unroll
    for (int i = 0; i < 4; i++)
        t[ty + i * 8][tx] = W[(k0 + ty + i * 8) * 1024 + n0 + tx];
    __syncthreads();
#pragma unroll
    for (int i = 0; i < 4; i++) {
        int n = n0 + ty + i * 8, k = k0 + tx;
        float x = t[tx][ty + i * 8];
        __half hi = __float2half_rn(x);
        g_Wthi[(size_t)(z * 1024 + n) * 1024 + k] = hi;
        g_Wtlo[(size_t)(z * 1024 + n) * 1024 + k] =
            __float2half_rn(x - __half2float(hi));
    }
}

// ---------------- fused QKV GEMM (mma.sync fp16 split) ----------------
// Q,K zones: 2-pass (Xhi*Whi + Xhi*Wlo), hi-only output.
// V zone: 3-pass (+ Xlo*Whi), hi+lo output.
#define GSTR 40                       // halves per smem row (32 + 8 pad)
#define GTEN (128 * GSTR * 2)         // 10240 B per tensor
#define GSTG (4 * GTEN)               // 40960 B per stage
#define GSM  (2 * GSTG)               // 81920 B

__global__ __launch_bounds__(256, 2) void k_gemm(
    const float* __restrict__ bq, const float* __restrict__ bk,
    const float* __restrict__ bv)
{
    extern __shared__ char sm[];
    uint32_t sb = s2u(sm);
    int tid = threadIdx.x, wid = tid >> 5, lane = tid & 31;
    int n0 = blockIdx.x * 128, m0 = blockIdx.y * 128;
    int wm = (wid & 3) * 32, wn = (wid >> 2) * 64;
    const bool three = (n0 >= 2048);   // V zone gets the 3rd pass

    const __half* s0p = g_Xhi + (size_t)m0 * 1024;
    const __half* s1p = g_Xlo + (size_t)m0 * 1024;
    const __half* s2p = g_Wthi + (size_t)n0 * 1024;
    const __half* s3p = g_Wtlo + (size_t)n0 * 1024;

    float c[2][8][4];
#pragma unroll
    for (int i = 0; i < 2; i++)
#pragma unroll
        for (int t = 0; t < 8; t++)
#pragma unroll
            for (int r = 0; r < 4; r++) c[i][t][r] = 0.0f;

    auto load_stage = [&](int buf, int k0) {
#pragma unroll
        for (int t = 0; t < 8; t++) {
            int id = tid + t * 256;                 // 0..2047
            int tensor = id >> 9, within = id & 511;
            int row = within >> 2, c4 = within & 3;
            const __half* src = (tensor == 0 ? s0p : tensor == 1 ? s1p :
                                 tensor == 2 ? s2p : s3p) +
                                (size_t)row * 1024 + k0 + c4 * 8;
            uint32_t dst = sb + buf * GSTG + tensor * GTEN + row * (GSTR * 2) + c4 * 16;
            cpa16(dst, src);
        }
        CP_COMMIT();
    };

    load_stage(0, 0);
    int arow = lane & 15, asel = (lane >> 4) * 8;
    int q8 = lane >> 3, r8 = lane & 7;
    int brow = ((q8 >> 1) ? 8 : 0) + r8, bsel = (q8 & 1) * 8;

    for (int kc = 0; kc < 32; kc++) {
        if (kc + 1 < 32) { load_stage((kc + 1) & 1, (kc + 1) * 32); CP_WAIT1(); }
        else CP_WAIT0();
        __syncthreads();
        uint32_t base = sb + (kc & 1) * GSTG;
#pragma unroll
        for (int ks = 0; ks < 2; ks++) {
            int koff = ks * 16;
            uint32_t ahi[2][4], alo[2][4];
#pragma unroll
            for (int i = 0; i < 2; i++) {
                uint32_t ad = base + ((wm + i * 16 + arow) * GSTR + koff + asel) * 2;
                ldm4(ahi[i], ad);
                if (three) ldm4(alo[i], ad + GTEN);
            }
#pragma unroll
            for (int j = 0; j < 4; j++) {
                uint32_t bhi[4], blo[4];
                uint32_t bd = base + 2 * GTEN + ((wn + j * 16 + brow) * GSTR + koff + bsel) * 2;
                ldm4(bhi, bd);
                ldm4(blo, bd + GTEN);
#pragma unroll
                for (int i = 0; i < 2; i++) {
                    mmaf16(c[i][2 * j],     ahi[i], bhi[0], bhi[1]);
                    mmaf16(c[i][2 * j + 1], ahi[i], bhi[2], bhi[3]);
                    mmaf16(c[i][2 * j],     ahi[i], blo[0], blo[1]);
                    mmaf16(c[i][2 * j + 1], ahi[i], blo[2], blo[3]);
                    if (three) {
                        mmaf16(c[i][2 * j],     alo[i], bhi[0], bhi[1]);
                        mmaf16(c[i][2 * j + 1], alo[i], bhi[2], bhi[3]);
                    }
                }
            }
        }
        __syncthreads();
    }

    // epilogue
    int g = lane >> 2, tg = lane & 3;
    int zone = n0 >> 10, nb = n0 & 1023;
    const float* bp = (zone == 0) ? bq : (zone == 1) ? bk : bv;
#pragma unroll
    for (int i = 0; i < 2; i++) {
        int mlo = m0 + wm + i * 16 + g;
#pragma unroll
        for (int t = 0; t < 8; t++) {
            int n = nb + wn + t * 8 + tg * 2;
            float b0v = bp[n], b1v = bp[n + 1];
            int hh = n >> 6, hd = n & 63;
#pragma unroll
            for (int rr = 0; rr < 2; rr++) {
                int m = mlo + rr * 8, bb = m >> 11, s = m & 2047;
                float f0 = c[i][t][rr * 2] + b0v;
                float f1 = c[i][t][rr * 2 + 1] + b1v;
                __half h0 = __float2half_rn(f0), h1 = __float2half_rn(f1);
                if (zone < 2) {
                    __half* Oh = zone ? g_Khi : g_Qhi;
                    size_t off = ((size_t)(bb * 16 + hh) * 2048 + s) * 64 + hd;
                    *(uint32_t*)(Oh + off) = packh2(h0, h1);
                } else {
                    __half l0 = __float2half_rn(f0 - __half2float(h0));
                    __half l1 = __float2half_rn(f1 - __half2float(h1));
                    size_t off = ((size_t)(bb * 16 + hh) * 64 + hd) * 2048 + s;
                    g_Vhi[off] = h0;        g_Vlo[off] = l0;
                    g_Vhi[off + 2048] = h1; g_Vlo[off + 2048] = l1;
                }
            }
        }
    }
}

// ---------------- flash attention (mma.sync fp16) ----------------
// QK^T: 1-pass (qhi*khi). PV: 2-pass (phi*vhi + phi*vlo).
#define AKV  8192
#define ATEN 9216                     // 64 * 72 * 2 B
#define ASTG (3 * ATEN)               // 27648 (K, Vhi, Vlo)
#define ASM  (AKV + 2 * ASTG)         // 63488

__global__ __launch_bounds__(256, 2) void k_attn(const float* __restrict__ mask,
                                                 float* __restrict__ out)
{
    extern __shared__ char sm[];
    uint32_t sb = s2u(sm);
    int tid = threadIdx.x, wid = tid >> 5, lane = tid & 31;
    int qt = blockIdx.x, h = blockIdx.y, b = blockIdx.z, bh = b * 16 + h;
    int wq = wid * 16;
    int g = lane >> 2, tg = lane & 3;
    int arow = lane & 15, asel = (lane >> 4) * 8;
    int q8 = lane >> 3, r8 = lane & 7;
    int brow = ((q8 >> 1) ? 8 : 0) + r8, bsel = (q8 & 1) * 8;

    const __half* Qh = g_Qhi + ((size_t)bh * 2048 + qt * 128) * 64;
    const __half* Kh = g_Khi + (size_t)bh * 2048 * 64;
    const __half* Vh = g_Vhi + (size_t)bh * 64 * 2048;
    const __half* Vl = g_Vlo + (size_t)bh * 64 * 2048;

    // stage Q (hi only) through KV buffer 0
#pragma unroll
    for (int t = 0; t < 4; t++) {
        int id = tid + t * 256;                     // 0..1023
        int row = id >> 3, c8 = id & 7;
        cpa16(sb + AKV + row * 144 + c8 * 16, Qh + (size_t)row * 64 + c8 * 8);
    }
    CP_COMMIT();
    float* msks = (float*)sm;
#pragma unroll
    for (int i = 0; i < 8; i++) {
        int col = tid + i * 256;
        msks[col] = mask[b * 2048 + col] * LOG2E + PSH;
    }
    CP_WAIT0();
    __syncthreads();

    uint32_t qhi[4][4];
#pragma unroll
    for (int kk = 0; kk < 4; kk++) {
        uint32_t ad = sb + AKV + ((wq + arow) * 72 + kk * 16 + asel) * 2;
        ldm4(qhi[kk], ad);
    }
    __syncthreads();

    auto load_kv = [&](int buf, int kt) {
#pragma unroll
        for (int t = 0; t < 6; t++) {
            int id = tid + t * 256;                 // 0..1535
            int tensor = id >> 9, within = id & 511;
            int row = within >> 3, c8 = within & 7;
            const __half* src;
            if (tensor == 0)      src = Kh + (size_t)(kt * 64 + row) * 64 + c8 * 8;
            else if (tensor == 1) src = Vh + (size_t)row * 2048 + kt * 64 + c8 * 8;
            else                  src = Vl + (size_t)row * 2048 + kt * 64 + c8 * 8;
            cpa16(sb + AKV + buf * ASTG + tensor * ATEN + row * 144 + c8 * 16, src);
        }
        CP_COMMIT();
    };

    float ctx[8][4];
#pragma unroll
    for (int t = 0; t < 8; t++)
#pragma unroll
        for (int r = 0; r < 4; r++) ctx[t][r] = 0.0f;
    float li0 = 0.0f, li1 = 0.0f;

    load_kv(0, 0);
    for (int kt = 0; kt < 32; kt++) {
        if (kt + 1 < 32) { load_kv((kt + 1) & 1, kt + 1); CP_WAIT1(); }
        else CP_WAIT0();
        __syncthreads();
        uint32_t base = sb + AKV + (kt & 1) * ASTG;

        // process this 64-wide kv tile in 4 groups of 16 kv columns
#pragma unroll
        for (int jg = 0; jg < 4; jg++) {
            float sc[2][4];
#pragma unroll
            for (int t = 0; t < 2; t++)
#pragma unroll
                for (int r = 0; r < 4; r++) sc[t][r] = 0.0f;

#pragma unroll
            for (int kk = 0; kk < 4; kk++) {
                uint32_t khi[4];
                ldm4(khi, base + ((jg * 16 + brow) * 72 + kk * 16 + bsel) * 2);
                mmaf16(sc[0], qhi[kk], khi[0], khi[1]);
                mmaf16(sc[1], qhi[kk], khi[2], khi[3]);
            }

            // softmax for these 16 columns -> A-fragment P (hi only)
            uint32_t phi[4];
#pragma unroll
            for (int t = 0; t < 2; t++) {
                int col = kt * 64 + jg * 16 + t * 8 + tg * 2;
                float m0v = msks[col], m1v = msks[col + 1];
                float p00 = ex2(fmaf(sc[t][0], SC2, m0v));
                float p01 = ex2(fmaf(sc[t][1], SC2, m1v));
                float p10 = ex2(fmaf(sc[t][2], SC2, m0v));
                float p11 = ex2(fmaf(sc[t][3], SC2, m1v));
                li0 += p00 + p01;
                li1 += p10 + p11;
                phi[t * 2]     = packh2(__float2half_rn(p00), __float2half_rn(p01));
                phi[t * 2 + 1] = packh2(__float2half_rn(p10), __float2half_rn(p11));
            }

            // ctx += P(16 cols) @ V chunk  (2-pass: vhi + vlo)
#pragma unroll
            for (int n4 = 0; n4 < 4; n4++) {
                uint32_t vhi[4], vlo[4];
                uint32_t vd = base + ATEN + ((n4 * 16 + brow) * 72 + jg * 16 + bsel) * 2;
                ldm4(vhi, vd);
                ldm4(vlo, vd + ATEN);
                mmaf16(ctx[2 * n4],     phi, vhi[0], vhi[1]);
                mmaf16(ctx[2 * n4 + 1], phi, vhi[2], vhi[3]);
                mmaf16(ctx[2 * n4],     phi, vlo[0], vlo[1]);
                mmaf16(ctx[2 * n4 + 1], phi, vlo[2], vlo[3]);
            }
        }
        __syncthreads();
    }

    // row sums across the 4-lane group, normalize, write out
    li0 += __shfl_xor_sync(0xFFFFFFFFu, li0, 1);
    li0 += __shfl_xor_sync(0xFFFFFFFFu, li0, 2);
    li1 += __shfl_xor_sync(0xFFFFFFFFu, li1, 1);
    li1 += __shfl_xor_sync(0xFFFFFFFFu, li1, 2);
    float inv0 = 1.0f / li0, inv1 = 1.0f / li1;
    int s0 = qt * 128 + wq + g;
    float* o0 = out + ((size_t)(b * 2048 + s0)) * 1024 + h * 64;
    float* o1 = o0 + 8 * 1024;
#pragma unroll
    for (int t = 0; t < 8; t++) {
        int hd = t * 8 + tg * 2;
        float2 v0 = { ctx[t][0] * inv0, ctx[t][1] * inv0 };
        float2 v1 = { ctx[t][2] * inv1, ctx[t][3] * inv1 };
        *(float2*)(o0 + hd) = v0;
        *(float2*)(o1 + hd) = v1;
    }
}

// ---------------- launch ----------------
extern "C" void kernel_launch(void* const* d_in, const int* in_sizes, int n_in,
                              void* d_out, int out_size)
{
    const float* hs = (const float*)d_in[0];
    const float* mask = (const float*)d_in[1];
    const float* Wq = (const float*)d_in[2];
    const float* bq = (const float*)d_in[3];
    const float* Wk = (const float*)d_in[4];
    const float* bk = (const float*)d_in[5];
    const float* Wv = (const float*)d_in[6];
    const float* bv = (const float*)d_in[7];
    float* out = (float*)d_out;

    k_split_x<<<4096, 256>>>((const float4*)hs);
    k_transw<<<dim3(32, 32, 3), dim3(32, 8)>>>(Wq, Wk, Wv);

    cudaFuncSetAttribute(k_gemm, cudaFuncAttributeMaxDynamicSharedMemorySize, GSM);
    k_gemm<<<dim3(24, 32), 256, GSM>>>(bq, bk, bv);

    cudaFuncSetAttribute(k_attn, cudaFuncAttributeMaxDynamicSharedMemorySize, ASM);
    k_attn<<<dim3(16, 16, 2), 256, ASM>>>(mask, out);
    (void)in_sizes; (void)n_in; (void)out_size;
}

// round 9
// speedup vs baseline: 1.3863x; 1.3863x over previous
#include <cuda_runtime.h>
#include <cuda_fp16.h>
#include <cstdint>

#define LOG2E 1.4426950408889634f
#define SC2   0.18033688011112042f   // 0.125 * LOG2E
#define PSH   9.0f                   // prob scale 2^9 (cancels in normalization)

__device__ __forceinline__ uint32_t s2u(const void* p) {
    uint32_t a;
    asm("{ .reg .u64 t; cvta.to.shared.u64 t, %1; cvt.u32.u64 %0, t; }" : "=r"(a) : "l"(p));
    return a;
}
__device__ __forceinline__ void ldm4(uint32_t (&r)[4], uint32_t addr) {
    asm volatile("ldmatrix.sync.aligned.m8n8.x4.shared.b16 {%0,%1,%2,%3}, [%4];"
        : "=r"(r[0]), "=r"(r[1]), "=r"(r[2]), "=r"(r[3]) : "r"(addr));
}
__device__ __forceinline__ void mmaf16(float (&c)[4], const uint32_t (&a)[4],
                                       uint32_t b0, uint32_t b1) {
    asm volatile("mma.sync.aligned.m16n8k16.row.col.f32.f16.f16.f32 "
        "{%0,%1,%2,%3}, {%4,%5,%6,%7}, {%8,%9}, {%0,%1,%2,%3};"
        : "+f"(c[0]), "+f"(c[1]), "+f"(c[2]), "+f"(c[3])
        : "r"(a[0]), "r"(a[1]), "r"(a[2]), "r"(a[3]), "r"(b0), "r"(b1));
}
__device__ __forceinline__ void cpa16(uint32_t dst, const void* src) {
    asm volatile("cp.async.cg.shared.global [%0], [%1], 16;" :: "r"(dst), "l"(src));
}
#define CP_COMMIT() asm volatile("cp.async.commit_group;" ::: "memory")
#define CP_WAIT0()  asm volatile("cp.async.wait_group 0;" ::: "memory")
#define CP_WAIT1()  asm volatile("cp.async.wait_group 1;" ::: "memory")

__device__ __forceinline__ float ex2(float x) {
    float y; asm("ex2.approx.f32 %0, %1;" : "=f"(y) : "f"(x)); return y;
}
__device__ __forceinline__ uint32_t packh2(__half a, __half b) {
    __half2 t = __halves2half2(a, b);
    return *reinterpret_cast<uint32_t*>(&t);
}

// ---------------- device scratch (no cudaMalloc) ----------------
__device__ __align__(16) __half g_Xhi[4096 * 1024];
__device__ __align__(16) __half g_Wthi[3072 * 1024];
__device__ __align__(16) __half g_Wtlo[3072 * 1024];
__device__ __align__(16) __half g_Qhi[32 * 2048 * 64];
__device__ __align__(16) __half g_Khi[32 * 2048 * 64];
__device__ __align__(16) __half g_Vhi[32 * 64 * 2048];  // transposed [bh][hd][s]

// ---------------- prep ----------------
__global__ __launch_bounds__(256) void k_split_x(const float4* __restrict__ X) {
    int i = blockIdx.x * 256 + threadIdx.x;
    float4 v = X[i];
    ((uint32_t*)g_Xhi)[2 * i] = packh2(__float2half_rn(v.x), __float2half_rn(v.y));
    ((uint32_t*)g_Xhi)[2 * i + 1] = packh2(__float2half_rn(v.z), __float2half_rn(v.w));
}

__global__ void k_transw(const float* __restrict__ Wq, const float* __restrict__ Wk,
                         const float* __restrict__ Wv) {
    __shared__ float t[32][33];
    int z = blockIdx.z;
    const float* W = (z == 0) ? Wq : (z == 1) ? Wk : Wv;
    int n0 = blockIdx.x * 32, k0 = blockIdx.y * 32;
    int tx = threadIdx.x, ty = threadIdx.y;
#pragma unroll
    for (int i = 0; i < 4; i++)
        t[ty + i * 8][tx] = W[(k0 + ty + i * 8) * 1024 + n0 + tx];
    __syncthreads();
#pragma unroll
    for (int i = 0; i < 4; i++) {
        int n = n0 + ty + i * 8, k = k0 + tx;
        float x = t[tx][ty + i * 8];
        __half hi = __float2half_rn(x);
        g_Wthi[(size_t)(z * 1024 + n) * 1024 + k] = hi;
        g_Wtlo[(size_t)(z * 1024 + n) * 1024 + k] =
            __float2half_rn(x - __half2float(hi));
    }
}

// ---------------- fused QKV GEMM (mma.sync fp16, 2-pass all zones) ----------------
// C = Xhi @ (Whi + Wlo) + bias.  3 smem tensors per stage: Xhi, Whi, Wlo.
#define GSTR 40                       // halves per smem row (32 + 8 pad)
#define GTEN (128 * GSTR * 2)         // 10240 B per tensor
#define GSTG (3 * GTEN)               // 30720 B per stage
#define GSM  (2 * GSTG)               // 61440 B

__global__ __launch_bounds__(256, 2) void k_gemm(
    const float* __restrict__ bq, const float* __restrict__ bk,
    const float* __restrict__ bv)
{
    extern __shared__ char sm[];
    uint32_t sb = s2u(sm);
    int tid = threadIdx.x, wid = tid >> 5, lane = tid & 31;
    int n0 = blockIdx.x * 128, m0 = blockIdx.y * 128;
    int wm = (wid & 3) * 32, wn = (wid >> 2) * 64;

    const __half* s0p = g_Xhi + (size_t)m0 * 1024;
    const __half* s1p = g_Wthi + (size_t)n0 * 1024;
    const __half* s2p = g_Wtlo + (size_t)n0 * 1024;

    float c[2][8][4];
#pragma unroll
    for (int i = 0; i < 2; i++)
#pragma unroll
        for (int t = 0; t < 8; t++)
#pragma unroll
            for (int r = 0; r < 4; r++) c[i][t][r] = 0.0f;

    auto load_stage = [&](int buf, int k0) {
#pragma unroll
        for (int t = 0; t < 6; t++) {
            int id = tid + t * 256;                 // 0..1535
            int tensor = id >> 9, within = id & 511;
            int row = within >> 2, c4 = within & 3;
            const __half* src = (tensor == 0 ? s0p : tensor == 1 ? s1p : s2p) +
                                (size_t)row * 1024 + k0 + c4 * 8;
            uint32_t dst = sb + buf * GSTG + tensor * GTEN + row * (GSTR * 2) + c4 * 16;
            cpa16(dst, src);
        }
        CP_COMMIT();
    };

    load_stage(0, 0);
    int arow = lane & 15, asel = (lane >> 4) * 8;
    int q8 = lane >> 3, r8 = lane & 7;
    int brow = ((q8 >> 1) ? 8 : 0) + r8, bsel = (q8 & 1) * 8;

    for (int kc = 0; kc < 32; kc++) {
        if (kc + 1 < 32) { load_stage((kc + 1) & 1, (kc + 1) * 32); CP_WAIT1(); }
        else CP_WAIT0();
        __syncthreads();
        uint32_t base = sb + (kc & 1) * GSTG;
#pragma unroll
        for (int ks = 0; ks < 2; ks++) {
            int koff = ks * 16;
            uint32_t ahi[2][4];
#pragma unroll
            for (int i = 0; i < 2; i++)
                ldm4(ahi[i], base + ((wm + i * 16 + arow) * GSTR + koff + asel) * 2);
#pragma unroll
            for (int j = 0; j < 4; j++) {
                uint32_t bhi[4], blo[4];
                uint32_t bd = base + GTEN + ((wn + j * 16 + brow) * GSTR + koff + bsel) * 2;
                ldm4(bhi, bd);
                ldm4(blo, bd + GTEN);
#pragma unroll
                for (int i = 0; i < 2; i++) {
                    mmaf16(c[i][2 * j],     ahi[i], bhi[0], bhi[1]);
                    mmaf16(c[i][2 * j + 1], ahi[i], bhi[2], bhi[3]);
                    mmaf16(c[i][2 * j],     ahi[i], blo[0], blo[1]);
                    mmaf16(c[i][2 * j + 1], ahi[i], blo[2], blo[3]);
                }
            }
        }
        __syncthreads();
    }

    // epilogue
    int g = lane >> 2, tg = lane & 3;
    int zone = n0 >> 10, nb = n0 & 1023;
    const float* bp = (zone == 0) ? bq : (zone == 1) ? bk : bv;
#pragma unroll
    for (int i = 0; i < 2; i++) {
        int mlo = m0 + wm + i * 16 + g;
#pragma unroll
        for (int t = 0; t < 8; t++) {
            int n = nb + wn + t * 8 + tg * 2;
            float b0v = bp[n], b1v = bp[n + 1];
            int hh = n >> 6, hd = n & 63;
#pragma unroll
            for (int rr = 0; rr < 2; rr++) {
                int m = mlo + rr * 8, bb = m >> 11, s = m & 2047;
                __half h0 = __float2half_rn(c[i][t][rr * 2] + b0v);
                __half h1 = __float2half_rn(c[i][t][rr * 2 + 1] + b1v);
                if (zone < 2) {
                    __half* Oh = zone ? g_Khi : g_Qhi;
                    size_t off = ((size_t)(bb * 16 + hh) * 2048 + s) * 64 + hd;
                    *(uint32_t*)(Oh + off) = packh2(h0, h1);
                } else {
                    size_t off = ((size_t)(bb * 16 + hh) * 64 + hd) * 2048 + s;
                    g_Vhi[off] = h0;
                    g_Vhi[off + 2048] = h1;
                }
            }
        }
    }
}

// ---------------- flash attention (mma.sync fp16, 1-pass QK, 1-pass PV) ----------------
#define AKV  8192
#define ATEN 9216                     // 64 * 72 * 2 B
#define ASTG (2 * ATEN)               // 18432 (K, Vhi)
#define ASM  (AKV + 2 * ASTG)         // 45056

__global__ __launch_bounds__(256, 3) void k_attn(const float* __restrict__ mask,
                                                 float* __restrict__ out)
{
    extern __shared__ char sm[];
    uint32_t sb = s2u(sm);
    int tid = threadIdx.x, wid = tid >> 5, lane = tid & 31;
    int qt = blockIdx.x, h = blockIdx.y, b = blockIdx.z, bh = b * 16 + h;
    int wq = wid * 16;
    int g = lane >> 2, tg = lane & 3;
    int arow = lane & 15, asel = (lane >> 4) * 8;
    int q8 = lane >> 3, r8 = lane & 7;
    int brow = ((q8 >> 1) ? 8 : 0) + r8, bsel = (q8 & 1) * 8;

    const __half* Qh = g_Qhi + ((size_t)bh * 2048 + qt * 128) * 64;
    const __half* Kh = g_Khi + (size_t)bh * 2048 * 64;
    const __half* Vh = g_Vhi + (size_t)bh * 64 * 2048;

    // stage Q (hi only) through KV buffer 0
#pragma unroll
    for (int t = 0; t < 4; t++) {
        int id = tid + t * 256;                     // 0..1023
        int row = id >> 3, c8 = id & 7;
        cpa16(sb + AKV + row * 144 + c8 * 16, Qh + (size_t)row * 64 + c8 * 8);
    }
    CP_COMMIT();
    float* msks = (float*)sm;
#pragma unroll
    for (int i = 0; i < 8; i++) {
        int col = tid + i * 256;
        msks[col] = mask[b * 2048 + col] * LOG2E + PSH;
    }
    CP_WAIT0();
    __syncthreads();

    uint32_t qhi[4][4];
#pragma unroll
    for (int kk = 0; kk < 4; kk++)
        ldm4(qhi[kk], sb + AKV + ((wq + arow) * 72 + kk * 16 + asel) * 2);
    __syncthreads();

    auto load_kv = [&](int buf, int kt) {
#pragma unroll
        for (int t = 0; t < 4; t++) {
            int id = tid + t * 256;                 // 0..1023
            int tensor = id >> 9, within = id & 511;
            int row = within >> 3, c8 = within & 7;
            const __half* src = tensor == 0
                ? Kh + (size_t)(kt * 64 + row) * 64 + c8 * 8
                : Vh + (size_t)row * 2048 + kt * 64 + c8 * 8;
            cpa16(sb + AKV + buf * ASTG + tensor * ATEN + row * 144 + c8 * 16, src);
        }
        CP_COMMIT();
    };

    float ctx[8][4];
#pragma unroll
    for (int t = 0; t < 8; t++)
#pragma unroll
        for (int r = 0; r < 4; r++) ctx[t][r] = 0.0f;
    float li0 = 0.0f, li1 = 0.0f;

    load_kv(0, 0);
    for (int kt = 0; kt < 32; kt++) {
        if (kt + 1 < 32) { load_kv((kt + 1) & 1, kt + 1); CP_WAIT1(); }
        else CP_WAIT0();
        __syncthreads();
        uint32_t base = sb + AKV + (kt & 1) * ASTG;

        // process this 64-wide kv tile in 4 groups of 16 kv columns
#pragma unroll
        for (int jg = 0; jg < 4; jg++) {
            float sc[2][4];
#pragma unroll
            for (int t = 0; t < 2; t++)
#pragma unroll
                for (int r = 0; r < 4; r++) sc[t][r] = 0.0f;

#pragma unroll
            for (int kk = 0; kk < 4; kk++) {
                uint32_t khi[4];
                ldm4(khi, base + ((jg * 16 + brow) * 72 + kk * 16 + bsel) * 2);
                mmaf16(sc[0], qhi[kk], khi[0], khi[1]);
                mmaf16(sc[1], qhi[kk], khi[2], khi[3]);
            }

            // softmax for these 16 columns -> A-fragment P (hi only)
            uint32_t phi[4];
#pragma unroll
            for (int t = 0; t < 2; t++) {
                int col = kt * 64 + jg * 16 + t * 8 + tg * 2;
                float m0v = msks[col], m1v = msks[col + 1];
                float p00 = ex2(fmaf(sc[t][0], SC2, m0v));
                float p01 = ex2(fmaf(sc[t][1], SC2, m1v));
                float p10 = ex2(fmaf(sc[t][2], SC2, m0v));
                float p11 = ex2(fmaf(sc[t][3], SC2, m1v));
                li0 += p00 + p01;
                li1 += p10 + p11;
                phi[t * 2]     = packh2(__float2half_rn(p00), __float2half_rn(p01));
                phi[t * 2 + 1] = packh2(__float2half_rn(p10), __float2half_rn(p11));
            }

            // ctx += P(16 cols) @ V chunk  (1-pass)
#pragma unroll
            for (int n4 = 0; n4 < 4; n4++) {
                uint32_t vhi[4];
                ldm4(vhi, base + ATEN + ((n4 * 16 + brow) * 72 + jg * 16 + bsel) * 2);
                mmaf16(ctx[2 * n4],     phi, vhi[0], vhi[1]);
                mmaf16(ctx[2 * n4 + 1], phi, vhi[2], vhi[3]);
            }
        }
        __syncthreads();
    }

    // row sums across the 4-lane group, normalize, write out
    li0 += __shfl_xor_sync(0xFFFFFFFFu, li0, 1);
    li0 += __shfl_xor_sync(0xFFFFFFFFu, li0, 2);
    li1 += __shfl_xor_sync(0xFFFFFFFFu, li1, 1);
    li1 += __shfl_xor_sync(0xFFFFFFFFu, li1, 2);
    float inv0 = 1.0f / li0, inv1 = 1.0f / li1;
    int s0 = qt * 128 + wq + g;
    float* o0 = out + ((size_t)(b * 2048 + s0)) * 1024 + h * 64;
    float* o1 = o0 + 8 * 1024;
#pragma unroll
    for (int t = 0; t < 8; t++) {
        int hd = t * 8 + tg * 2;
        float2 v0 = { ctx[t][0] * inv0, ctx[t][1] * inv0 };
        float2 v1 = { ctx[t][2] * inv1, ctx[t][3] * inv1 };
        *(float2*)(o0 + hd) = v0;
        *(float2*)(o1 + hd) = v1;
    }
}

// ---------------- launch ----------------
extern "C" void kernel_launch(void* const* d_in, const int* in_sizes, int n_in,
                              void* d_out, int out_size)
{
    const float* hs = (const float*)d_in[0];
    const float* mask = (const float*)d_in[1];
    const float* Wq = (const float*)d_in[2];
    const float* bq = (const float*)d_in[3];
    const float* Wk = (const float*)d_in[4];
    const float* bk = (const float*)d_in[5];
    const float* Wv = (const float*)d_in[6];
    const float* bv = (const float*)d_in[7];
    float* out = (float*)d_out;

    k_split_x<<<4096, 256>>>((const float4*)hs);
    k_transw<<<dim3(32, 32, 3), dim3(32, 8)>>>(Wq, Wk, Wv);

    cudaFuncSetAttribute(k_gemm, cudaFuncAttributeMaxDynamicSharedMemorySize, GSM);
    k_gemm<<<dim3(24, 32), 256, GSM>>>(bq, bk, bv);

    cudaFuncSetAttribute(k_attn, cudaFuncAttributeMaxDynamicSharedMemorySize, ASM);
    k_attn<<<dim3(16, 16, 2), 256, ASM>>>(mask, out);
    (void)in_sizes; (void)n_in; (void)out_size;
}

// round 10
// speedup vs baseline: 2.2124x; 1.5959x over previous
#include <cuda_runtime.h>
#include <cuda_fp16.h>
#include <cstdint>

#define LOG2E 1.4426950408889634f
#define SC2   0.18033688011112042f   // 0.125 * LOG2E
#define PSH   9.0f                   // prob scale 2^9 (cancels in normalization)

__device__ __forceinline__ uint32_t s2u(const void* p) {
    uint32_t a;
    asm("{ .reg .u64 t; cvta.to.shared.u64 t, %1; cvt.u32.u64 %0, t; }" : "=r"(a) : "l"(p));
    return a;
}
__device__ __forceinline__ void ldm4(uint32_t (&r)[4], uint32_t addr) {
    asm volatile("ldmatrix.sync.aligned.m8n8.x4.shared.b16 {%0,%1,%2,%3}, [%4];"
        : "=r"(r[0]), "=r"(r[1]), "=r"(r[2]), "=r"(r[3]) : "r"(addr));
}
__device__ __forceinline__ void mmaf16(float (&c)[4], const uint32_t (&a)[4],
                                       uint32_t b0, uint32_t b1) {
    asm volatile("mma.sync.aligned.m16n8k16.row.col.f32.f16.f16.f32 "
        "{%0,%1,%2,%3}, {%4,%5,%6,%7}, {%8,%9}, {%0,%1,%2,%3};"
        : "+f"(c[0]), "+f"(c[1]), "+f"(c[2]), "+f"(c[3])
        : "r"(a[0]), "r"(a[1]), "r"(a[2]), "r"(a[3]), "r"(b0), "r"(b1));
}
__device__ __forceinline__ void cpa16(uint32_t dst, const void* src) {
    asm volatile("cp.async.cg.shared.global [%0], [%1], 16;" :: "r"(dst), "l"(src));
}
#define CP_COMMIT() asm volatile("cp.async.commit_group;" ::: "memory")
#define CP_WAIT0()  asm volatile("cp.async.wait_group 0;" ::: "memory")
#define CP_WAIT1()  asm volatile("cp.async.wait_group 1;" ::: "memory")

__device__ __forceinline__ float ex2(float x) {
    float y; asm("ex2.approx.f32 %0, %1;" : "=f"(y) : "f"(x)); return y;
}
__device__ __forceinline__ uint32_t packh2(__half a, __half b) {
    __half2 t = __halves2half2(a, b);
    return *reinterpret_cast<uint32_t*>(&t);
}

// ---------------- device scratch (no cudaMalloc) ----------------
__device__ __align__(16) __half g_Xhi[4096 * 1024];
__device__ __align__(16) __half g_Wthi[3072 * 1024];
__device__ __align__(16) __half g_Qhi[32 * 2048 * 64];
__device__ __align__(16) __half g_Khi[32 * 2048 * 64];
__device__ __align__(16) __half g_Vhi[32 * 64 * 2048];  // transposed [bh][hd][s]

// ---------------- prep ----------------
__global__ __launch_bounds__(256) void k_split_x(const float4* __restrict__ X) {
    int i = blockIdx.x * 256 + threadIdx.x;
    float4 v = X[i];
    ((uint32_t*)g_Xhi)[2 * i] = packh2(__float2half_rn(v.x), __float2half_rn(v.y));
    ((uint32_t*)g_Xhi)[2 * i + 1] = packh2(__float2half_rn(v.z), __float2half_rn(v.w));
}

__global__ void k_transw(const float* __restrict__ Wq, const float* __restrict__ Wk,
                         const float* __restrict__ Wv) {
    __shared__ float t[32][33];
    int z = blockIdx.z;
    const float* W = (z == 0) ? Wq : (z == 1) ? Wk : Wv;
    int n0 = blockIdx.x * 32, k0 = blockIdx.y * 32;
    int tx = threadIdx.x, ty = threadIdx.y;
#pragma unroll
    for (int i = 0; i < 4; i++)
        t[ty + i * 8][tx] = W[(k0 + ty + i * 8) * 1024 + n0 + tx];
    __syncthreads();
#pragma unroll
    for (int i = 0; i < 4; i++) {
        int n = n0 + ty + i * 8, k = k0 + tx;
        g_Wthi[(size_t)(z * 1024 + n) * 1024 + k] = __float2half_rn(t[tx][ty + i * 8]);
    }
}

// ---------------- fused QKV GEMM (mma.sync fp16, 1-pass) ----------------
// C = Xhi @ Whi + bias.  2 smem tensors per stage: Xhi, Whi.
#define GSTR 40                       // halves per smem row (32 + 8 pad)
#define GTEN (128 * GSTR * 2)         // 10240 B per tensor
#define GSTG (2 * GTEN)               // 20480 B per stage
#define GSM  (2 * GSTG)               // 40960 B

__global__ __launch_bounds__(256, 3) void k_gemm(
    const float* __restrict__ bq, const float* __restrict__ bk,
    const float* __restrict__ bv)
{
    extern __shared__ char sm[];
    uint32_t sb = s2u(sm);
    int tid = threadIdx.x, wid = tid >> 5, lane = tid & 31;
    int n0 = blockIdx.x * 128, m0 = blockIdx.y * 128;
    int wm = (wid & 3) * 32, wn = (wid >> 2) * 64;

    const __half* s0p = g_Xhi + (size_t)m0 * 1024;
    const __half* s1p = g_Wthi + (size_t)n0 * 1024;

    float c[2][8][4];
#pragma unroll
    for (int i = 0; i < 2; i++)
#pragma unroll
        for (int t = 0; t < 8; t++)
#pragma unroll
            for (int r = 0; r < 4; r++) c[i][t][r] = 0.0f;

    auto load_stage = [&](int buf, int k0) {
#pragma unroll
        for (int t = 0; t < 4; t++) {
            int id = tid + t * 256;                 // 0..1023
            int tensor = id >> 9, within = id & 511;
            int row = within >> 2, c4 = within & 3;
            const __half* src = (tensor == 0 ? s0p : s1p) +
                                (size_t)row * 1024 + k0 + c4 * 8;
            uint32_t dst = sb + buf * GSTG + tensor * GTEN + row * (GSTR * 2) + c4 * 16;
            cpa16(dst, src);
        }
        CP_COMMIT();
    };

    load_stage(0, 0);
    int arow = lane & 15, asel = (lane >> 4) * 8;
    int q8 = lane >> 3, r8 = lane & 7;
    int brow = ((q8 >> 1) ? 8 : 0) + r8, bsel = (q8 & 1) * 8;

    for (int kc = 0; kc < 32; kc++) {
        if (kc + 1 < 32) { load_stage((kc + 1) & 1, (kc + 1) * 32); CP_WAIT1(); }
        else CP_WAIT0();
        __syncthreads();
        uint32_t base = sb + (kc & 1) * GSTG;
#pragma unroll
        for (int ks = 0; ks < 2; ks++) {
            int koff = ks * 16;
            uint32_t ahi[2][4];
#pragma unroll
            for (int i = 0; i < 2; i++)
                ldm4(ahi[i], base + ((wm + i * 16 + arow) * GSTR + koff + asel) * 2);
#pragma unroll
            for (int j = 0; j < 4; j++) {
                uint32_t bhi[4];
                ldm4(bhi, base + GTEN + ((wn + j * 16 + brow) * GSTR + koff + bsel) * 2);
#pragma unroll
                for (int i = 0; i < 2; i++) {
                    mmaf16(c[i][2 * j],     ahi[i], bhi[0], bhi[1]);
                    mmaf16(c[i][2 * j + 1], ahi[i], bhi[2], bhi[3]);
                }
            }
        }
        __syncthreads();
    }

    // epilogue
    int g = lane >> 2, tg = lane & 3;
    int zone = n0 >> 10, nb = n0 & 1023;
    const float* bp = (zone == 0) ? bq : (zone == 1) ? bk : bv;
#pragma unroll
    for (int i = 0; i < 2; i++) {
        int mlo = m0 + wm + i * 16 + g;
#pragma unroll
        for (int t = 0; t < 8; t++) {
            int n = nb + wn + t * 8 + tg * 2;
            float b0v = bp[n], b1v = bp[n + 1];
            int hh = n >> 6, hd = n & 63;
#pragma unroll
            for (int rr = 0; rr < 2; rr++) {
                int m = mlo + rr * 8, bb = m >> 11, s = m & 2047;
                __half h0 = __float2half_rn(c[i][t][rr * 2] + b0v);
                __half h1 = __float2half_rn(c[i][t][rr * 2 + 1] + b1v);
                if (zone < 2) {
                    __half* Oh = zone ? g_Khi : g_Qhi;
                    size_t off = ((size_t)(bb * 16 + hh) * 2048 + s) * 64 + hd;
                    *(uint32_t*)(Oh + off) = packh2(h0, h1);
                } else {
                    size_t off = ((size_t)(bb * 16 + hh) * 64 + hd) * 2048 + s;
                    g_Vhi[off] = h0;
                    g_Vhi[off + 2048] = h1;
                }
            }
        }
    }
}

// ---------------- flash attention (mma.sync fp16, 1-pass QK, 1-pass PV) ----------------
#define AKV  8192
#define ATEN 9216                     // 64 * 72 * 2 B
#define ASTG (2 * ATEN)               // 18432 (K, Vhi)
#define ASM  (AKV + 2 * ASTG)         // 45056

__global__ __launch_bounds__(256, 3) void k_attn(const float* __restrict__ mask,
                                                 float* __restrict__ out)
{
    extern __shared__ char sm[];
    uint32_t sb = s2u(sm);
    int tid = threadIdx.x, wid = tid >> 5, lane = tid & 31;
    int qt = blockIdx.x, h = blockIdx.y, b = blockIdx.z, bh = b * 16 + h;
    int wq = wid * 16;
    int g = lane >> 2, tg = lane & 3;
    int arow = lane & 15, asel = (lane >> 4) * 8;
    int q8 = lane >> 3, r8 = lane & 7;
    int brow = ((q8 >> 1) ? 8 : 0) + r8, bsel = (q8 & 1) * 8;

    const __half* Qh = g_Qhi + ((size_t)bh * 2048 + qt * 128) * 64;
    const __half* Kh = g_Khi + (size_t)bh * 2048 * 64;
    const __half* Vh = g_Vhi + (size_t)bh * 64 * 2048;

    // stage Q (hi only) through KV buffer 0
#pragma unroll
    for (int t = 0; t < 4; t++) {
        int id = tid + t * 256;                     // 0..1023
        int row = id >> 3, c8 = id & 7;
        cpa16(sb + AKV + row * 144 + c8 * 16, Qh + (size_t)row * 64 + c8 * 8);
    }
    CP_COMMIT();
    float* msks = (float*)sm;
#pragma unroll
    for (int i = 0; i < 8; i++) {
        int col = tid + i * 256;
        msks[col] = mask[b * 2048 + col] * LOG2E + PSH;
    }
    CP_WAIT0();
    __syncthreads();

    uint32_t qhi[4][4];
#pragma unroll
    for (int kk = 0; kk < 4; kk++)
        ldm4(qhi[kk], sb + AKV + ((wq + arow) * 72 + kk * 16 + asel) * 2);
    __syncthreads();

    auto load_kv = [&](int buf, int kt) {
#pragma unroll
        for (int t = 0; t < 4; t++) {
            int id = tid + t * 256;                 // 0..1023
            int tensor = id >> 9, within = id & 511;
            int row = within >> 3, c8 = within & 7;
            const __half* src = tensor == 0
                ? Kh + (size_t)(kt * 64 + row) * 64 + c8 * 8
                : Vh + (size_t)row * 2048 + kt * 64 + c8 * 8;
            cpa16(sb + AKV + buf * ASTG + tensor * ATEN + row * 144 + c8 * 16, src);
        }
        CP_COMMIT();
    };

    float ctx[8][4];
#pragma unroll
    for (int t = 0; t < 8; t++)
#pragma unroll
        for (int r = 0; r < 4; r++) ctx[t][r] = 0.0f;
    float li0 = 0.0f, li1 = 0.0f;

    load_kv(0, 0);
    for (int kt = 0; kt < 32; kt++) {
        if (kt + 1 < 32) { load_kv((kt + 1) & 1, kt + 1); CP_WAIT1(); }
        else CP_WAIT0();
        __syncthreads();
        uint32_t base = sb + AKV + (kt & 1) * ASTG;

        // process this 64-wide kv tile in 4 groups of 16 kv columns
#pragma unroll
        for (int jg = 0; jg < 4; jg++) {
            float sc[2][4];
#pragma unroll
            for (int t = 0; t < 2; t++)
#pragma unroll
                for (int r = 0; r < 4; r++) sc[t][r] = 0.0f;

#pragma unroll
            for (int kk = 0; kk < 4; kk++) {
                uint32_t khi[4];
                ldm4(khi, base + ((jg * 16 + brow) * 72 + kk * 16 + bsel) * 2);
                mmaf16(sc[0], qhi[kk], khi[0], khi[1]);
                mmaf16(sc[1], qhi[kk], khi[2], khi[3]);
            }

            // softmax for these 16 columns -> A-fragment P (hi only)
            uint32_t phi[4];
#pragma unroll
            for (int t = 0; t < 2; t++) {
                int col = kt * 64 + jg * 16 + t * 8 + tg * 2;
                float m0v = msks[col], m1v = msks[col + 1];
                float p00 = ex2(fmaf(sc[t][0], SC2, m0v));
                float p01 = ex2(fmaf(sc[t][1], SC2, m1v));
                float p10 = ex2(fmaf(sc[t][2], SC2, m0v));
                float p11 = ex2(fmaf(sc[t][3], SC2, m1v));
                li0 += p00 + p01;
                li1 += p10 + p11;
                phi[t * 2]     = packh2(__float2half_rn(p00), __float2half_rn(p01));
                phi[t * 2 + 1] = packh2(__float2half_rn(p10), __float2half_rn(p11));
            }

            // ctx += P(16 cols) @ V chunk  (1-pass)
#pragma unroll
            for (int n4 = 0; n4 < 4; n4++) {
                uint32_t vhi[4];
                ldm4(vhi, base + ATEN + ((n4 * 16 + brow) * 72 + jg * 16 + bsel) * 2);
                mmaf16(ctx[2 * n4],     phi, vhi[0], vhi[1]);
                mmaf16(ctx[2 * n4 + 1], phi, vhi[2], vhi[3]);
            }
        }
        __syncthreads();
    }

    // row sums across the 4-lane group, normalize, write out
    li0 += __shfl_xor_sync(0xFFFFFFFFu, li0, 1);
    li0 += __shfl_xor_sync(0xFFFFFFFFu, li0, 2);
    li1 += __shfl_xor_sync(0xFFFFFFFFu, li1, 1);
    li1 += __shfl_xor_sync(0xFFFFFFFFu, li1, 2);
    float inv0 = 1.0f / li0, inv1 = 1.0f / li1;
    int s0 = qt * 128 + wq + g;
    float* o0 = out + ((size_t)(b * 2048 + s0)) * 1024 + h * 64;
    float* o1 = o0 + 8 * 1024;
#pragma unroll
    for (int t = 0; t < 8; t++) {
        int hd = t * 8 + tg * 2;
        float2 v0 = { ctx[t][0] * inv0, ctx[t][1] * inv0 };
        float2 v1 = { ctx[t][2] * inv1, ctx[t][3] * inv1 };
        *(float2*)(o0 + hd) = v0;
        *(float2*)(o1 + hd) = v1;
    }
}

// ---------------- launch ----------------
extern "C" void kernel_launch(void* const* d_in, const int* in_sizes, int n_in,
                              void* d_out, int out_size)
{
    const float* hs = (const float*)d_in[0];
    const float* mask = (const float*)d_in[1];
    const float* Wq = (const float*)d_in[2];
    const float* bq = (const float*)d_in[3];
    const float* Wk = (const float*)d_in[4];
    const float* bk = (const float*)d_in[5];
    const float* Wv = (const float*)d_in[6];
    const float* bv = (const float*)d_in[7];
    float* out = (float*)d_out;

    k_split_x<<<4096, 256>>>((const float4*)hs);
    k_transw<<<dim3(32, 32, 3), dim3(32, 8)>>>(Wq, Wk, Wv);

    cudaFuncSetAttribute(k_gemm, cudaFuncAttributeMaxDynamicSharedMemorySize, GSM);
    k_gemm<<<dim3(24, 32), 256, GSM>>>(bq, bk, bv);

    cudaFuncSetAttribute(k_attn, cudaFuncAttributeMaxDynamicSharedMemorySize, ASM);
    k_attn<<<dim3(16, 16, 2), 256, ASM>>>(mask, out);
    (void)in_sizes; (void)n_in; (void)out_size;
}